// round 9
// baseline (speedup 1.0000x reference)
#include <cuda_runtime.h>
#include <cuda_bf16.h>
#include <math.h>

// ---------------------------------------------------------------------------
// CGCA branch, fully collapsed and single-kernel (plus a counter memset):
//   gc = adj·fc1·blockdiag(w2)·w1·avg = B·avg  (linear chain up to relu).
// Blocks 0..16      : build row j of B[17,512]; flag completion.
// Blocks 17..17+4095: pool 8 (n,c) rows each; last-finishing block of each
//                     batch computes out[b,:] = sigmoid(fc2·relu(B·avg_b)).
// Counters zeroed per launch via captured cudaMemsetAsync (replay-safe).
// ---------------------------------------------------------------------------

#define J    17
#define C    512
#define CA   272
#define HW   3136          // 56*56
#define HW4  784           // HW/4
#define NEG  (-9e15f)
#define JJ   289           // J*J

// flatnonzero(ADJ) — 49 entries
__constant__ int NZ[49] = {
      0,   1,
     17,  18,  19,
     35,  36,  40,
     54,  55,  57,
     71,  72,  73,
     89,  90,
    104, 105, 108, 109,
    125, 126, 127,
    143, 144, 147, 148, 152,
    162, 169,
    180, 181,
    197, 198, 199,
    212, 215, 216,
    229, 234, 235,
    251, 252, 253,
    269, 270,
    280, 281, 288
};

// scratch (static device globals — no allocation)
__device__ float g_avg[256 * C];     // pooled features, max batch 256
__device__ float g_B[J * C];         // collapsed linear map [17, 512]
__device__ int   g_sync[260];        // [0] = B-ready count; [4+b] = batch tickets

__global__ __launch_bounds__(256, 4) void fused_kernel(
    const float* __restrict__ x,     // [n*C*HW]
    const float* __restrict__ e,     // [49]
    const float* __restrict__ fc1,   // [J, CA]
    const float* __restrict__ w2,    // [CA, J]  (blockdiag groups [16,J,J])
    const float* __restrict__ w1,    // [CA, C]
    const float* __restrict__ fc2,   // [C, J]
    float* __restrict__ out,         // [n, C]
    int rows)
{
    __shared__ float adjs[JJ];
    __shared__ float arow[J];
    __shared__ float F[CA];
    __shared__ float T[CA];
    __shared__ float avgs[C];
    __shared__ float gcs[J];
    __shared__ int   ticket_s;

    const int t = threadIdx.x;

    if (blockIdx.x < J) {
        // ================= precompute branch: row j of B =================
        const int j = blockIdx.x;

        // fill ALL 289 slots (289 > 256: must loop — R7 bug)
        for (int idx = t; idx < JJ; idx += 256) adjs[idx] = NEG;
        __syncthreads();
        if (t < 49) adjs[NZ[t]] = e[t];
        __syncthreads();

        if (t == 0) {
            float m = NEG;
#pragma unroll
            for (int k = 0; k < J; k++) m = fmaxf(m, adjs[j * J + k]);
            float s = 0.f, tmp[J];
#pragma unroll
            for (int k = 0; k < J; k++) { tmp[k] = expf(adjs[j * J + k] - m); s += tmp[k]; }
            float inv = 1.0f / s;
#pragma unroll
            for (int k = 0; k < J; k++) arow[k] = tmp[k] * inv;
        }
        __syncthreads();

        // F[k] = sum_{j2} arow[j2] * fc1[j2, k]
        for (int idx = t; idx < CA; idx += 256) {
            float s = 0.f;
#pragma unroll
            for (int j2 = 0; j2 < J; j2++) s += arow[j2] * fc1[j2 * CA + idx];
            F[idx] = s;
        }
        __syncthreads();

        // T[g*17+i] = sum_o F[g*17+o] * w2[(g*17+o)*17 + i]
        for (int idx = t; idx < CA; idx += 256) {
            int g = idx / J, i = idx % J;
            float s = 0.f;
#pragma unroll
            for (int o = 0; o < J; o++) s += F[g * J + o] * w2[(g * J + o) * J + i];
            T[idx] = s;
        }
        __syncthreads();

        // B[j, c] = sum_k T[k] * w1[k, c] ; thread covers c = t and t+256.
        {
            float a0 = 0.f, a1 = 0.f, a2 = 0.f, a3 = 0.f;
            float b0 = 0.f, b1 = 0.f, b2 = 0.f, b3 = 0.f;
#pragma unroll
            for (int k = 0; k < CA / 4; k++) {
                const float* r0 = w1 + (4 * k + 0) * C;
                const float* r1 = w1 + (4 * k + 1) * C;
                const float* r2 = w1 + (4 * k + 2) * C;
                const float* r3 = w1 + (4 * k + 3) * C;
                a0 += T[4 * k + 0] * r0[t];
                a1 += T[4 * k + 1] * r1[t];
                a2 += T[4 * k + 2] * r2[t];
                a3 += T[4 * k + 3] * r3[t];
                b0 += T[4 * k + 0] * r0[t + 256];
                b1 += T[4 * k + 1] * r1[t + 256];
                b2 += T[4 * k + 2] * r2[t + 256];
                b3 += T[4 * k + 3] * r3[t + 256];
            }
            g_B[j * C + t]       = (a0 + a1) + (a2 + a3);
            g_B[j * C + t + 256] = (b0 + b1) + (b2 + b3);
        }

        // publish B row
        __threadfence();
        __syncthreads();
        if (t == 0) atomicAdd(&g_sync[0], 1);
        return;
    }

    // ================= pool branch: 8 warps, one (n,c) row each ==========
    {
        const int rb   = blockIdx.x - J;            // row-block 0..4095
        const int warp = rb * 8 + (t >> 5);
        const int lane = t & 31;
        const int b    = rb >> 6;                   // 64 row-blocks per batch

        if (warp < rows) {
            const float4* p = reinterpret_cast<const float4*>(x) + (size_t)warp * HW4;

            float4 a = make_float4(0.f, 0.f, 0.f, 0.f);
#pragma unroll
            for (int i = 0; i < 24; i++) {
                float4 v = __ldcs(&p[lane + i * 32]);
                a.x += v.x; a.y += v.y; a.z += v.z; a.w += v.w;
            }
            if (lane < 16) {               // 784 - 24*32 = 16 tail vec4s
                float4 v = __ldcs(&p[768 + lane]);
                a.x += v.x; a.y += v.y; a.z += v.z; a.w += v.w;
            }
            float s = (a.x + a.y) + (a.z + a.w);
#pragma unroll
            for (int o = 16; o; o >>= 1) s += __shfl_xor_sync(0xffffffffu, s, o);

            if (lane == 0) g_avg[warp] = s * (1.0f / (float)HW);
        }

        // publish this block's avg rows, take a ticket for batch b
        __threadfence();
        __syncthreads();
        if (t == 0) ticket_s = atomicAdd(&g_sync[4 + b], 1);
        __syncthreads();
        if (ticket_s != 63) return;        // not the last block of this batch

        // ---- last block of batch b: finish the channel attention ----
        if (t == 0) {                      // wait for all 17 B rows
            while (*((volatile int*)&g_sync[0]) < J) { }
        }
        __syncthreads();
        __threadfence();                   // acquire for g_B / g_avg reads

        avgs[t]       = g_avg[b * C + t];
        avgs[t + 256] = g_avg[b * C + t + 256];
        __syncthreads();

        // gc[j] = relu(dot(B[j,:], avg)) — 8 warps cover 17 rows
        {
            const int wid = t >> 5;
            for (int j = wid; j < J; j += 8) {
                const float* wr = g_B + (size_t)j * C;
                float s = 0.f;
#pragma unroll
                for (int k = lane; k < C; k += 32) s += avgs[k] * wr[k];
#pragma unroll
                for (int off = 16; off; off >>= 1)
                    s += __shfl_xor_sync(0xffffffffu, s, off);
                if (lane == 0) gcs[j] = fmaxf(s, 0.f);
            }
        }
        __syncthreads();

        // out[b, c] = sigmoid(dot(gc, fc2[c,:])) — c = t and t+256
#pragma unroll
        for (int h = 0; h < 2; h++) {
            int c = t + h * 256;
            const float* wr = fc2 + (size_t)c * J;
            float s = 0.f;
#pragma unroll
            for (int j = 0; j < J; j++) s += gcs[j] * wr[j];
            out[b * C + c] = 1.0f / (1.0f + expf(-s));
        }
    }
}

// ---------------------------------------------------------------------------
extern "C" void kernel_launch(void* const* d_in, const int* in_sizes, int n_in,
                              void* d_out, int out_size)
{
    const float* x    = (const float*)d_in[0];
    const float* e    = (const float*)d_in[1];
    const float* w1   = (const float*)d_in[2];
    const float* w2   = (const float*)d_in[3];
    const float* fc1w = (const float*)d_in[4];
    const float* fc2w = (const float*)d_in[5];
    float* out = (float*)d_out;

    int n    = in_sizes[0] / (C * HW);   // 64
    int rows = n * C;                    // 32768

    void* syncp;
    cudaGetSymbolAddress(&syncp, g_sync);
    cudaMemsetAsync(syncp, 0, sizeof(int) * (4 + n));   // replay-safe reset

    int grid = J + (rows + 7) / 8;       // 17 precompute + 4096 pool blocks
    fused_kernel<<<grid, 256>>>(x, e, fc1w, w2, w1, fc2w, out, rows);
}